// round 12
// baseline (speedup 1.0000x reference)
#include <cuda_runtime.h>
#include <cuda_bf16.h>

#define MAXN 8192
__device__ float4 g_pt[MAXN];   // x, y, ell, theta/tau per point

#define TPB 128
#define ILP 4            // i-lanes per thread = 2 packed f32x2 pairs
#define NPK (ILP / 2)
#define JT  32

typedef unsigned long long u64;

#define PK(o,lo,hi)    asm("mov.b64 %0, {%1,%2};" : "=l"(o) : "f"(lo), "f"(hi))
#define UNPK(lo,hi,in) asm("mov.b64 {%0,%1}, %2;" : "=f"(lo), "=f"(hi) : "l"(in))

// Entire per-(packed-pair x j) interaction in ONE asm block: no register
// allocation seams, movs collapse to aliases, setp runs parallel to rsqrt.
#define PAIR_BODY(FL, FT, JX, JY, JL, JT_, SJ, NX, NY, NL, NT, EPS, MAG, NMAG, NEG1, CUT) \
    asm("{\n\t" \
        ".reg .b64 dx, dy, t0, d2, r, f, dl, u, t1, w, dth;\n\t" \
        ".reg .f32 d2l, d2h, rl, rh;\n\t" \
        ".reg .pred p, q;\n\t" \
        "add.rn.f32x2 dx, %2, %7;\n\t" \
        "add.rn.f32x2 dy, %3, %8;\n\t" \
        "fma.rn.f32x2 t0, dy, dy, %11;\n\t" \
        "fma.rn.f32x2 d2, dx, dx, t0;\n\t" \
        "mov.b64 {d2l, d2h}, d2;\n\t" \
        "rsqrt.approx.f32 rl, d2l;\n\t" \
        "rsqrt.approx.f32 rh, d2h;\n\t" \
        "setp.gt.f32 p, d2l, %15;\n\t" \
        "setp.gt.f32 q, d2h, %15;\n\t" \
        "selp.f32 rl, 0f00000000, rl, p;\n\t" \
        "selp.f32 rh, 0f00000000, rh, q;\n\t" \
        "mov.b64 r, {rl, rh};\n\t" \
        "mul.rn.f32x2 f, r, %6;\n\t" \
        "add.rn.f32x2 dl, %4, %9;\n\t" \
        "add.rn.f32x2 u,  %5, %10;\n\t" \
        "add.rn.f32x2 t1, u, %12;\n\t" \
        "add.rn.f32x2 w,  t1, %13;\n\t" \
        "fma.rn.f32x2 dth, w, %14, u;\n\t" \
        "fma.rn.f32x2 %0, f, dl, %0;\n\t" \
        "fma.rn.f32x2 %1, f, dth, %1;\n\t" \
        "}" \
        : "+l"(FL), "+l"(FT) \
        : "l"(JX), "l"(JY), "l"(JL), "l"(JT_), "l"(SJ), \
          "l"(NX), "l"(NY), "l"(NL), "l"(NT), \
          "l"(EPS), "l"(MAG), "l"(NMAG), "l"(NEG1), "f"(CUT))

__device__ __forceinline__ u64 dup2f(float v) {
    return (u64)__float_as_uint(v) * 0x100000001ull;
}

__global__ void precompute_xy(const float* __restrict__ ell,
                              const float* __restrict__ theta,
                              float* __restrict__ out, int N) {
    const float INV_TAU = 0.15915494309189533577f;
    int i = blockIdx.x * blockDim.x + threadIdx.x;
    if (i < N) {
        float e = ell[i];
        float t = theta[i];
        float r = expf(e);
        float sn, cs;
        sincosf(t, &sn, &cs);
        float ax = r * (fabsf(cs) + 1e-10f);
        float ay = r * (fabsf(sn) + 1e-10f);
        float4 p;
        p.x = (cs >= 0.f) ? ax : -ax;
        p.y = (sn >= 0.f) ? ay : -ay;
        p.z = e;
        p.w = t * INV_TAU;                 // normalized theta (turns)
        g_pt[i] = p;
        out[i]     = 0.f;                  // fused output zeroing
        out[N + i] = 0.f;
    }
}

__global__ void __launch_bounds__(TPB)
force_kernel(const float* __restrict__ s, const unsigned char* __restrict__ frozen,
             float* __restrict__ out, int N)
{
    // j-tile: {dup(x),dup(y)} and {dup(ell),dup(tn)} as 128-bit rows + dup(s)
    __shared__ ulonglong2 sXY[JT];
    __shared__ ulonglong2 sLT[JT];
    __shared__ u64        sS[JT];

    const float CUT2  = 6.854101966249685f;      // phi^4
    const float TAU_F = 6.28318530717958647692f;

    int tid = threadIdx.x;
    int ibase = blockIdx.x * (TPB * ILP) + tid;

    // ---- prefetch i-data first (overlap LDG latency with j-tile fill) ----
    float4 qi[NPK][2];
#pragma unroll
    for (int p = 0; p < NPK; p++)
#pragma unroll
        for (int h = 0; h < 2; h++) {
            int i = ibase + (2 * p + h) * TPB;
            qi[p][h] = (i < N) ? g_pt[i] : make_float4(1e30f, 1e30f, 0.f, 0.f);
        }

    // ---- j tile ----
    if (tid < JT) {
        int j = blockIdx.y * JT + tid;
        float x = 1e30f, y = 1e30f, l = 0.f, t = 0.f, sv = 0.f;
        if (j < N) {
            float4 p = g_pt[j];
            x = p.x; y = p.y; l = p.z; t = p.w; sv = s[j];
        }
        ulonglong2 a; a.x = dup2f(x); a.y = dup2f(y);
        ulonglong2 b; b.x = dup2f(l); b.y = dup2f(t);
        sXY[tid] = a;
        sLT[tid] = b;
        sS[tid]  = dup2f(sv);
    }

    u64 nx[NPK], ny[NPK], nl[NPK], nt[NPK], fl[NPK], ft[NPK];
#pragma unroll
    for (int p = 0; p < NPK; p++) {
        PK(nx[p], -qi[p][0].x, -qi[p][1].x);
        PK(ny[p], -qi[p][0].y, -qi[p][1].y);
        PK(nl[p], -qi[p][0].z, -qi[p][1].z);
        PK(nt[p], -qi[p][0].w, -qi[p][1].w);
        fl[p] = 0ull;
        ft[p] = 0ull;
    }

    __syncthreads();

    const u64 EPS2  = dup2f(1e-30f);
    const u64 NEG1  = dup2f(-1.0f);
    const u64 MAG2  = dup2f(12582912.0f);    //  1.5*2^23
    const u64 NMAG2 = dup2f(-12582912.0f);

#pragma unroll 4
    for (int jj = 0; jj < JT; jj++) {
        ulonglong2 XY = sXY[jj];             // LDS.128
        ulonglong2 LT = sLT[jj];             // LDS.128
        u64        Sj = sS[jj];              // LDS.64
#pragma unroll
        for (int p = 0; p < NPK; p++) {
            PAIR_BODY(fl[p], ft[p], XY.x, XY.y, LT.x, LT.y, Sj,
                      nx[p], ny[p], nl[p], nt[p],
                      EPS2, MAG2, NMAG2, NEG1, CUT2);
        }
    }

#pragma unroll
    for (int p = 0; p < NPK; p++) {
        float flo, fhi, tlo, thi;
        UNPK(flo, fhi, fl[p]);
        UNPK(tlo, thi, ft[p]);
        float fls[2] = {flo, fhi};
        float fts[2] = {tlo, thi};
#pragma unroll
        for (int h = 0; h < 2; h++) {
            int i = ibase + (2 * p + h) * TPB;
            if (i < N) {
                float m = frozen[i] ? 0.f : s[i];
                atomicAdd(&out[i],     m * fls[h]);
                atomicAdd(&out[N + i], (m * TAU_F) * fts[h]);  // turns -> radians
            }
        }
    }
}

extern "C" void kernel_launch(void* const* d_in, const int* in_sizes, int n_in,
                              void* d_out, int out_size) {
    const float*         ell    = (const float*)d_in[0];
    const float*         theta  = (const float*)d_in[1];
    const float*         s      = (const float*)d_in[2];
    const unsigned char* frozen = (const unsigned char*)d_in[3];
    float* out = (float*)d_out;
    int N = in_sizes[0];

    precompute_xy<<<(N + 255) / 256, 256>>>(ell, theta, out, N);

    dim3 grid((N + TPB * ILP - 1) / (TPB * ILP), (N + JT - 1) / JT);
    force_kernel<<<grid, TPB>>>(s, frozen, out, N);
}

// round 13
// speedup vs baseline: 1.1303x; 1.1303x over previous
#include <cuda_runtime.h>
#include <cuda_bf16.h>

#define MAXN 8192
__device__ float4 g_pt[MAXN];   // x, y, ell, theta/tau per point

#define TPB 128
#define ILP 4            // i-lanes per thread = 2 packed f32x2 pairs
#define NPK (ILP / 2)
#define JT  16           // smaller j-tile => 2048 CTAs => ~40 resident warps/SM

typedef unsigned long long u64;

#define PK(o,lo,hi)    asm("mov.b64 %0, {%1,%2};" : "=l"(o) : "f"(lo), "f"(hi))
#define UNPK(lo,hi,in) asm("mov.b64 {%0,%1}, %2;" : "=f"(lo), "=f"(hi) : "l"(in))

// Entire per-(packed-pair x j) interaction in ONE asm block: no register
// allocation seams, movs collapse to aliases, setp runs parallel to rsqrt.
#define PAIR_BODY(FL, FT, JX, JY, JL, JT_, SJ, NX, NY, NL, NT, EPS, MAG, NMAG, NEG1, CUT) \
    asm("{\n\t" \
        ".reg .b64 dx, dy, t0, d2, r, f, dl, u, t1, w, dth;\n\t" \
        ".reg .f32 d2l, d2h, rl, rh;\n\t" \
        ".reg .pred p, q;\n\t" \
        "add.rn.f32x2 dx, %2, %7;\n\t" \
        "add.rn.f32x2 dy, %3, %8;\n\t" \
        "fma.rn.f32x2 t0, dy, dy, %11;\n\t" \
        "fma.rn.f32x2 d2, dx, dx, t0;\n\t" \
        "mov.b64 {d2l, d2h}, d2;\n\t" \
        "rsqrt.approx.f32 rl, d2l;\n\t" \
        "rsqrt.approx.f32 rh, d2h;\n\t" \
        "setp.gt.f32 p, d2l, %15;\n\t" \
        "setp.gt.f32 q, d2h, %15;\n\t" \
        "selp.f32 rl, 0f00000000, rl, p;\n\t" \
        "selp.f32 rh, 0f00000000, rh, q;\n\t" \
        "mov.b64 r, {rl, rh};\n\t" \
        "mul.rn.f32x2 f, r, %6;\n\t" \
        "add.rn.f32x2 dl, %4, %9;\n\t" \
        "add.rn.f32x2 u,  %5, %10;\n\t" \
        "add.rn.f32x2 t1, u, %12;\n\t" \
        "add.rn.f32x2 w,  t1, %13;\n\t" \
        "fma.rn.f32x2 dth, w, %14, u;\n\t" \
        "fma.rn.f32x2 %0, f, dl, %0;\n\t" \
        "fma.rn.f32x2 %1, f, dth, %1;\n\t" \
        "}" \
        : "+l"(FL), "+l"(FT) \
        : "l"(JX), "l"(JY), "l"(JL), "l"(JT_), "l"(SJ), \
          "l"(NX), "l"(NY), "l"(NL), "l"(NT), \
          "l"(EPS), "l"(MAG), "l"(NMAG), "l"(NEG1), "f"(CUT))

__device__ __forceinline__ u64 dup2f(float v) {
    return (u64)__float_as_uint(v) * 0x100000001ull;
}

__global__ void precompute_xy(const float* __restrict__ ell,
                              const float* __restrict__ theta,
                              float* __restrict__ out, int N) {
    const float INV_TAU = 0.15915494309189533577f;
    int i = blockIdx.x * blockDim.x + threadIdx.x;
    if (i < N) {
        float e = ell[i];
        float t = theta[i];
        float r = expf(e);
        float sn, cs;
        sincosf(t, &sn, &cs);
        float ax = r * (fabsf(cs) + 1e-10f);
        float ay = r * (fabsf(sn) + 1e-10f);
        float4 p;
        p.x = (cs >= 0.f) ? ax : -ax;
        p.y = (sn >= 0.f) ? ay : -ay;
        p.z = e;
        p.w = t * INV_TAU;                 // normalized theta (turns)
        g_pt[i] = p;
        out[i]     = 0.f;                  // fused output zeroing
        out[N + i] = 0.f;
    }
}

__global__ void __launch_bounds__(TPB)
force_kernel(const float* __restrict__ s, const unsigned char* __restrict__ frozen,
             float* __restrict__ out, int N)
{
    // j-tile: {dup(x),dup(y)} and {dup(ell),dup(tn)} as 128-bit rows + dup(s)
    __shared__ ulonglong2 sXY[JT];
    __shared__ ulonglong2 sLT[JT];
    __shared__ u64        sS[JT];

    const float CUT2  = 6.854101966249685f;      // phi^4
    const float TAU_F = 6.28318530717958647692f;

    int tid = threadIdx.x;
    int ibase = blockIdx.x * (TPB * ILP) + tid;

    // ---- prefetch i-data first (overlap LDG latency with j-tile fill) ----
    float4 qi[NPK][2];
#pragma unroll
    for (int p = 0; p < NPK; p++)
#pragma unroll
        for (int h = 0; h < 2; h++) {
            int i = ibase + (2 * p + h) * TPB;
            qi[p][h] = (i < N) ? g_pt[i] : make_float4(1e30f, 1e30f, 0.f, 0.f);
        }

    // ---- j tile ----
    if (tid < JT) {
        int j = blockIdx.y * JT + tid;
        float x = 1e30f, y = 1e30f, l = 0.f, t = 0.f, sv = 0.f;
        if (j < N) {
            float4 p = g_pt[j];
            x = p.x; y = p.y; l = p.z; t = p.w; sv = s[j];
        }
        ulonglong2 a; a.x = dup2f(x); a.y = dup2f(y);
        ulonglong2 b; b.x = dup2f(l); b.y = dup2f(t);
        sXY[tid] = a;
        sLT[tid] = b;
        sS[tid]  = dup2f(sv);
    }

    u64 nx[NPK], ny[NPK], nl[NPK], nt[NPK], fl[NPK], ft[NPK];
#pragma unroll
    for (int p = 0; p < NPK; p++) {
        PK(nx[p], -qi[p][0].x, -qi[p][1].x);
        PK(ny[p], -qi[p][0].y, -qi[p][1].y);
        PK(nl[p], -qi[p][0].z, -qi[p][1].z);
        PK(nt[p], -qi[p][0].w, -qi[p][1].w);
        fl[p] = 0ull;
        ft[p] = 0ull;
    }

    __syncthreads();

    const u64 EPS2  = dup2f(1e-30f);
    const u64 NEG1  = dup2f(-1.0f);
    const u64 MAG2  = dup2f(12582912.0f);    //  1.5*2^23
    const u64 NMAG2 = dup2f(-12582912.0f);

#pragma unroll 8
    for (int jj = 0; jj < JT; jj++) {
        ulonglong2 XY = sXY[jj];             // LDS.128
        ulonglong2 LT = sLT[jj];             // LDS.128
        u64        Sj = sS[jj];              // LDS.64
#pragma unroll
        for (int p = 0; p < NPK; p++) {
            PAIR_BODY(fl[p], ft[p], XY.x, XY.y, LT.x, LT.y, Sj,
                      nx[p], ny[p], nl[p], nt[p],
                      EPS2, MAG2, NMAG2, NEG1, CUT2);
        }
    }

#pragma unroll
    for (int p = 0; p < NPK; p++) {
        float flo, fhi, tlo, thi;
        UNPK(flo, fhi, fl[p]);
        UNPK(tlo, thi, ft[p]);
        float fls[2] = {flo, fhi};
        float fts[2] = {tlo, thi};
#pragma unroll
        for (int h = 0; h < 2; h++) {
            int i = ibase + (2 * p + h) * TPB;
            if (i < N) {
                float m = frozen[i] ? 0.f : s[i];
                atomicAdd(&out[i],     m * fls[h]);
                atomicAdd(&out[N + i], (m * TAU_F) * fts[h]);  // turns -> radians
            }
        }
    }
}

extern "C" void kernel_launch(void* const* d_in, const int* in_sizes, int n_in,
                              void* d_out, int out_size) {
    const float*         ell    = (const float*)d_in[0];
    const float*         theta  = (const float*)d_in[1];
    const float*         s      = (const float*)d_in[2];
    const unsigned char* frozen = (const unsigned char*)d_in[3];
    float* out = (float*)d_out;
    int N = in_sizes[0];

    precompute_xy<<<(N + 255) / 256, 256>>>(ell, theta, out, N);

    dim3 grid((N + TPB * ILP - 1) / (TPB * ILP), (N + JT - 1) / JT);
    force_kernel<<<grid, TPB>>>(s, frozen, out, N);
}